// round 16
// baseline (speedup 1.0000x reference)
#include <cuda_runtime.h>
#include <cuda_fp16.h>
#include <cstdint>

// ---------------- problem dims ----------------
constexpr int B_ = 4, E_ = 8, C_ = 2048, D_ = 1024, F_ = 2816;

// Packed tiles: A 128x64 halfs (16KB), B 128x64 halfs (16KB), SW128-swizzled.
constexpr int TILE_A = 16384;
constexpr int TILE_B = 16384;

// ---------------- device scratch (allocation-free) ----------------
__device__ __half g_xa [(size_t)B_ * E_ * C_ * D_];     // X tiles [be][mb 16][kb 16]
__device__ __half g_wa [(size_t)E_ * 44 * 16 * 8192];   // W1|W3 tiles [e][nb 44][kb 16]
__device__ __half g_w2a[(size_t)E_ * 8 * 44 * 8192];    // W2 tiles [e][nb 8][kb 44]
__device__ __half g_ha [(size_t)B_ * E_ * C_ * F_];     // H tiles [be][mb 16][kb 44]

// ---------------- PTX helpers ----------------
__device__ __forceinline__ uint32_t smem_u32(const void* p) {
    return (uint32_t)__cvta_generic_to_shared(p);
}
__device__ __forceinline__ uint32_t swz(uint32_t off) { return off ^ ((off >> 3) & 0x70); }

__device__ __forceinline__ void bulk_cp(uint32_t dst, const void* src, uint32_t bytes,
                                        uint32_t mbar) {
    asm volatile(
        "cp.async.bulk.shared::cluster.global.mbarrier::complete_tx::bytes "
        "[%0], [%1], %2, [%3];"
        ::"r"(dst), "l"(src), "r"(bytes), "r"(mbar) : "memory");
}
__device__ __forceinline__ void mbar_init(uint32_t a, uint32_t cnt) {
    asm volatile("mbarrier.init.shared.b64 [%0], %1;" ::"r"(a), "r"(cnt) : "memory");
}
__device__ __forceinline__ void mbar_expect_tx(uint32_t a, uint32_t bytes) {
    asm volatile("mbarrier.arrive.expect_tx.shared.b64 _, [%0], %1;"
                 ::"r"(a), "r"(bytes) : "memory");
}
__device__ __forceinline__ void mbar_wait(uint32_t a, uint32_t parity) {
    asm volatile(
        "{\n\t.reg .pred P;\n"
        "WL_%=:\n\t"
        "mbarrier.try_wait.parity.acquire.cta.shared::cta.b64 P, [%0], %1, 0x989680;\n\t"
        "@P bra WD_%=;\n\t"
        "bra WL_%=;\n"
        "WD_%=:\n\t}"
        ::"r"(a), "r"(parity) : "memory");
}
__device__ __forceinline__ void ldsm4(uint32_t* r, uint32_t addr) {
    asm volatile("ldmatrix.sync.aligned.m8n8.x4.shared.b16 {%0,%1,%2,%3}, [%4];"
                 : "=r"(r[0]), "=r"(r[1]), "=r"(r[2]), "=r"(r[3])
                 : "r"(addr));
}
__device__ __forceinline__ void mma16816(float* d, const uint32_t* a, uint32_t b0, uint32_t b1) {
    asm volatile(
        "mma.sync.aligned.m16n8k16.row.col.f32.f16.f16.f32 "
        "{%0,%1,%2,%3}, {%4,%5,%6,%7}, {%8,%9}, {%0,%1,%2,%3};"
        : "+f"(d[0]), "+f"(d[1]), "+f"(d[2]), "+f"(d[3])
        : "r"(a[0]), "r"(a[1]), "r"(a[2]), "r"(a[3]), "r"(b0), "r"(b1));
}

// ---------------- unified pack kernel (round-15, unchanged) ----------------
constexpr int NB_X  = 8192;
constexpr int NB_W  = 22528;
constexpr int NB_ALL = NB_X + 3 * NB_W;   // 75776

__device__ void pack_x_blk(const float4* __restrict__ x, int bi) {
    const int kb = bi & 15, mb = (bi >> 4) & 15, be = bi >> 8;
    const float4* src = x + ((size_t)be * C_ + mb * 128) * (D_ / 4) + kb * 16;
    char* dst = (char*)g_xa + (((size_t)be * 16 + mb) * 16 + kb) * TILE_A;
    const int tid = threadIdx.x;
#pragma unroll
    for (int j = 0; j < 8; j++) {
        int t = tid + j * 256;
        int r = t >> 4, c = t & 15;
        float4 v = src[(size_t)r * (D_ / 4) + c];
        uint2 p;
        __half2 h0 = __floats2half2_rn(v.x, v.y);
        __half2 h1 = __floats2half2_rn(v.z, v.w);
        p.x = *reinterpret_cast<uint32_t*>(&h0);
        p.y = *reinterpret_cast<uint32_t*>(&h1);
        *reinterpret_cast<uint2*>(dst + swz(r * 128 + c * 8)) = p;
    }
}

__device__ void pack_w13_blk(const float* __restrict__ w, int rowoff, int bi,
                             float t[32][33]) {
    const int fb = bi % 88, db = (bi / 88) % 32, e = bi / (88 * 32);
    const int f0 = fb * 32, d0 = db * 32;
    const float* src = w + (size_t)e * D_ * F_;
    const int tx = threadIdx.x & 31, ty = threadIdx.x >> 5;
#pragma unroll
    for (int i = 0; i < 4; i++)
        t[ty + 8 * i][tx] = src[(size_t)(d0 + ty + 8 * i) * F_ + f0 + tx];
    __syncthreads();
    const int lin = threadIdx.x;
#pragma unroll
    for (int i = 0; i < 2; i++) {
        int idx = lin + 256 * i;
        int fl = idx >> 4, dp = idx & 15;
        int n = f0 + fl;
        int nb = n >> 6, row = (n & 63) + rowoff;
        int d = d0 + 2 * dp;
        int kb = d >> 6, cd = d & 63;
        char* dst = (char*)g_wa + (((size_t)e * 44 + nb) * 16 + kb) * TILE_B;
        *reinterpret_cast<__half2*>(dst + swz(row * 128 + cd * 2)) =
            __floats2half2_rn(t[2 * dp][fl], t[2 * dp + 1][fl]);
    }
}

__device__ void pack_w2_blk(const float* __restrict__ w, int bi, float t[32][33]) {
    const int db = bi % 32, fb = (bi / 32) % 88, e = bi / (32 * 88);
    const int d0 = db * 32, f0 = fb * 32;
    const float* src = w + (size_t)e * F_ * D_;
    const int tx = threadIdx.x & 31, ty = threadIdx.x >> 5;
#pragma unroll
    for (int i = 0; i < 4; i++)
        t[ty + 8 * i][tx] = src[(size_t)(f0 + ty + 8 * i) * D_ + d0 + tx];
    __syncthreads();
    const int lin = threadIdx.x;
#pragma unroll
    for (int i = 0; i < 2; i++) {
        int idx = lin + 256 * i;
        int dl = idx >> 4, fp = idx & 15;
        int n = d0 + dl;
        int nb = n >> 7, row = n & 127;
        int f = f0 + 2 * fp;
        int kb = f >> 6, cf = f & 63;
        char* dst = (char*)g_w2a + (((size_t)e * 8 + nb) * 44 + kb) * TILE_B;
        *reinterpret_cast<__half2*>(dst + swz(row * 128 + cf * 2)) =
            __floats2half2_rn(t[2 * fp][dl], t[2 * fp + 1][dl]);
    }
}

__global__ __launch_bounds__(256) void pack_all(const float4* __restrict__ x,
                                                const float* __restrict__ w1,
                                                const float* __restrict__ w3,
                                                const float* __restrict__ w2) {
    __shared__ float t[32][33];
    const int b = blockIdx.x;
    if (b < NB_X) {
        pack_x_blk(x, b);
    } else if (b < NB_X + NB_W) {
        pack_w13_blk(w1, 0, b - NB_X, t);
    } else if (b < NB_X + 2 * NB_W) {
        pack_w13_blk(w3, 64, b - NB_X - NB_W, t);
    } else {
        pack_w2_blk(w2, b - NB_X - 2 * NB_W, t);
    }
}

// ============================================================
// mma.sync GEMM: 256 threads, CTA tile 128x128, BK=64, 3 stages x 32KB,
// 2 CTAs/SM, whole-tile bulk G2S, pair-unrolled mainloop, AND
// CTA MERGING: each CTA processes TWO adjacent n-blocks with one
// continuous pipeline (B tiles are contiguous across nblks; A tiles repeat).
// Mid-kernel epilogue between halves overlaps the next half's DMAs.
// ============================================================
constexpr int STG   = TILE_A + TILE_B;   // 32768
constexpr int DYNSM = 3 * STG;           // 98304

template <int G1>
__global__ __launch_bounds__(256, 2) void gemm_mma(float* __restrict__ out) {
    extern __shared__ __align__(128) char smem[];
    __shared__ __align__(8) uint64_t fullb[3];

    const int tid  = threadIdx.x;
    const int wid  = tid >> 5;
    const int lane = tid & 31;
    const int be   = blockIdx.z, e = be & 7;
    const int mblk = blockIdx.y;
    const int nblk2 = blockIdx.x;        // pair of n-blocks

    constexpr int NKH = G1 ? 16 : 44;    // stages per half (both even)
    constexpr int NKT = 2 * NKH;         // total stages per CTA

    const char* Atile;
    const char* Btile;                   // base of FIRST half's tiles; contiguous across halves
    if (G1) {
        Atile = (const char*)g_xa + (((size_t)be * 16 + mblk) * 16) * TILE_A;
        Btile = (const char*)g_wa + (((size_t)e * 44 + nblk2 * 2) * 16) * TILE_B;
    } else {
        Atile = (const char*)g_ha  + (((size_t)be * 16 + mblk) * 44) * TILE_A;
        Btile = (const char*)g_w2a + (((size_t)e * 8 + nblk2 * 2) * 44) * TILE_B;
    }

    const uint32_t sb = smem_u32(smem);
    const uint32_t fb = smem_u32(fullb);

    if (tid == 0) {
#pragma unroll
        for (int i = 0; i < 3; i++) mbar_init(fb + 8 * i, 1);
    }
    __syncthreads();

    auto issue = [&](int kt) {
        const int s = kt % 3;
        const int akb = G1 ? (kt & 15) : (kt < 44 ? kt : kt - 44);
        mbar_expect_tx(fb + 8 * s, STG);
        bulk_cp(sb + s * STG, Atile + (size_t)akb * TILE_A, TILE_A, fb + 8 * s);
        bulk_cp(sb + s * STG + TILE_A, Btile + (size_t)kt * TILE_B, TILE_B, fb + 8 * s);
    };

    if (tid == 0) { issue(0); issue(1); issue(2); }

    const int wm = wid >> 2;             // 0..1 : M rows [wm*64, +64)
    const int wn = wid & 3;              // 0..3
    const int lr = lane & 15;
    const int lk = (lane >> 4) * 16;
    const int lr4 = lane >> 2;
    const int c0  = (lane & 3) * 2;

    float acc0[4][2][4], acc1[4][2][4];
#pragma unroll
    for (int i = 0; i < 4; i++)
#pragma unroll
        for (int j = 0; j < 2; j++)
#pragma unroll
            for (int q = 0; q < 4; q++) { acc0[i][j][q] = 0.f; acc1[i][j][q] = 0.f; }

    auto consume = [&](int kt) {
        const int s = kt % 3;
        mbar_wait(fb + 8 * s, (kt / 3) & 1);
        const uint32_t sA = sb + s * STG;
        const uint32_t sB = sA + TILE_A;
#pragma unroll
        for (int kk = 0; kk < 4; kk++) {
            uint32_t af[4][4];
#pragma unroll
            for (int mt = 0; mt < 4; mt++)
                ldsm4(af[mt], sA + swz((wm * 64 + mt * 16 + lr) * 128 + kk * 32 + lk));

            uint32_t b0r[4], b1r[4];
            if (G1) {
                ldsm4(b0r, sB + swz((wn * 16 + lr) * 128 + kk * 32 + lk));        // gate
                ldsm4(b1r, sB + swz((64 + wn * 16 + lr) * 128 + kk * 32 + lk));   // up
            } else {
                ldsm4(b0r, sB + swz((wn * 32 + lr) * 128 + kk * 32 + lk));
                ldsm4(b1r, sB + swz((wn * 32 + 16 + lr) * 128 + kk * 32 + lk));
            }
#pragma unroll
            for (int mt = 0; mt < 4; mt++)
#pragma unroll
                for (int hi = 0; hi < 2; hi++) {
                    mma16816(acc0[mt][hi], af[mt], b0r[hi], b0r[hi + 2]);
                    mma16816(acc1[mt][hi], af[mt], b1r[hi], b1r[hi + 2]);
                }
        }
    };

    // epilogue for one half (h = 0 or 1); scattered stores, no smem use.
    auto epilogue = [&](int h) {
        if (G1) {
            // SwiGLU -> packed H tile, H kb = nblk2*2 + h
            char* dst = (char*)g_ha +
                        (((size_t)be * 16 + mblk) * 44 + nblk2 * 2 + h) * TILE_A;
#pragma unroll
            for (int mt = 0; mt < 4; mt++) {
#pragma unroll
                for (int hh = 0; hh < 2; hh++) {
                    const int r128 = wm * 64 + mt * 16 + hh * 8 + lr4;
#pragma unroll
                    for (int hi = 0; hi < 2; hi++) {
                        const int nc = wn * 16 + hi * 8 + c0;   // 0..63
                        float g0 = acc0[mt][hi][2 * hh + 0], g1 = acc0[mt][hi][2 * hh + 1];
                        float u0 = acc1[mt][hi][2 * hh + 0], u1 = acc1[mt][hi][2 * hh + 1];
                        float h0 = u0 * g0 / (1.0f + __expf(-g0));
                        float h1 = u1 * g1 / (1.0f + __expf(-g1));
                        *reinterpret_cast<__half2*>(dst + swz(r128 * 128 + nc * 2)) =
                            __floats2half2_rn(h0, h1);
                    }
                }
            }
        } else {
            const int rbase = mblk * 128 + wm * 64 + lr4;
            const int n0    = (nblk2 * 2 + h) * 128;
#pragma unroll
            for (int mt = 0; mt < 4; mt++) {
#pragma unroll
                for (int hh = 0; hh < 2; hh++) {
                    const size_t row = (size_t)be * C_ + rbase + mt * 16 + hh * 8;
                    float* orow = out + row * D_ + n0 + wn * 32 + c0;
#pragma unroll
                    for (int hi = 0; hi < 2; hi++) {
                        *reinterpret_cast<float2*>(orow + hi * 8) =
                            make_float2(acc0[mt][hi][2 * hh + 0], acc0[mt][hi][2 * hh + 1]);
                        *reinterpret_cast<float2*>(orow + 16 + hi * 8) =
                            make_float2(acc1[mt][hi][2 * hh + 0], acc1[mt][hi][2 * hh + 1]);
                    }
                }
            }
        }
        // reset accumulators for next half
#pragma unroll
        for (int i = 0; i < 4; i++)
#pragma unroll
            for (int j = 0; j < 2; j++)
#pragma unroll
                for (int q = 0; q < 4; q++) { acc0[i][j][q] = 0.f; acc1[i][j][q] = 0.f; }
    };

    // pair-unrolled mainloop over BOTH halves; pipeline never drains.
    for (int kt = 0; kt < NKT; kt += 2) {
        if (kt >= 2) {
            __syncthreads();
            if (tid == 0) {
                issue(kt + 1);                     // buffer freed by stage kt-2
                if (kt + 2 < NKT) issue(kt + 2);   // buffer freed by stage kt-1
            }
        }
        consume(kt);
        consume(kt + 1);
        if (kt + 2 == NKH) epilogue(0);            // half-1 done; DMAs of half 2 in flight
    }
    epilogue(1);
}

// ---------------- launch ----------------
extern "C" void kernel_launch(void* const* d_in, const int* in_sizes, int n_in,
                              void* d_out, int out_size) {
    const float* x  = (const float*)d_in[0];
    const float* w1 = (const float*)d_in[1];
    const float* w3 = (const float*)d_in[2];
    const float* w2 = (const float*)d_in[3];
    float* out = (float*)d_out;

    cudaFuncSetAttribute(gemm_mma<1>, cudaFuncAttributeMaxDynamicSharedMemorySize, DYNSM);
    cudaFuncSetAttribute(gemm_mma<0>, cudaFuncAttributeMaxDynamicSharedMemorySize, DYNSM);

    pack_all<<<NB_ALL, 256>>>((const float4*)x, w1, w3, w2);

    gemm_mma<1><<<dim3(22, 16, 32), 256, DYNSM>>>(nullptr);   // 2 F-blocks per CTA
    gemm_mma<0><<<dim3(4, 16, 32), 256, DYNSM>>>(out);        // 2 D-blocks per CTA
}

// round 17
// speedup vs baseline: 1.0348x; 1.0348x over previous
#include <cuda_runtime.h>
#include <cuda_fp16.h>
#include <cstdint>

// ---------------- problem dims ----------------
constexpr int B_ = 4, E_ = 8, C_ = 2048, D_ = 1024, F_ = 2816;

// Packed tiles: A 128x64 halfs (16KB), B 128x64 halfs (16KB), SW128-swizzled.
constexpr int TILE_A = 16384;
constexpr int TILE_B = 16384;

// ---------------- device scratch (allocation-free) ----------------
__device__ __half g_xa [(size_t)B_ * E_ * C_ * D_];     // X tiles [be][mb 16][kb 16]
__device__ __half g_wa [(size_t)E_ * 44 * 16 * 8192];   // W1|W3 tiles [e][nb 44][kb 16]
__device__ __half g_w2a[(size_t)E_ * 8 * 44 * 8192];    // W2 tiles [e][nb 8][kb 44]
__device__ __half g_ha [(size_t)B_ * E_ * C_ * F_];     // H tiles [be][mb 16][kb 44]

// ---------------- PTX helpers ----------------
__device__ __forceinline__ uint32_t smem_u32(const void* p) {
    return (uint32_t)__cvta_generic_to_shared(p);
}
__device__ __forceinline__ uint32_t swz(uint32_t off) { return off ^ ((off >> 3) & 0x70); }

__device__ __forceinline__ void bulk_cp(uint32_t dst, const void* src, uint32_t bytes,
                                        uint32_t mbar) {
    asm volatile(
        "cp.async.bulk.shared::cluster.global.mbarrier::complete_tx::bytes "
        "[%0], [%1], %2, [%3];"
        ::"r"(dst), "l"(src), "r"(bytes), "r"(mbar) : "memory");
}
__device__ __forceinline__ void bulk_s2g(void* gdst, uint32_t ssrc, uint32_t bytes) {
    asm volatile(
        "cp.async.bulk.global.shared::cta.bulk_group [%0], [%1], %2;"
        ::"l"(gdst), "r"(ssrc), "r"(bytes) : "memory");
}
__device__ __forceinline__ void bulk_commit() {
    asm volatile("cp.async.bulk.commit_group;" ::: "memory");
}
__device__ __forceinline__ void bulk_wait0() {
    asm volatile("cp.async.bulk.wait_group 0;" ::: "memory");
}
__device__ __forceinline__ void fence_async_smem() {
    asm volatile("fence.proxy.async.shared::cta;" ::: "memory");
}
__device__ __forceinline__ void mbar_init(uint32_t a, uint32_t cnt) {
    asm volatile("mbarrier.init.shared.b64 [%0], %1;" ::"r"(a), "r"(cnt) : "memory");
}
__device__ __forceinline__ void mbar_expect_tx(uint32_t a, uint32_t bytes) {
    asm volatile("mbarrier.arrive.expect_tx.shared.b64 _, [%0], %1;"
                 ::"r"(a), "r"(bytes) : "memory");
}
__device__ __forceinline__ void mbar_wait(uint32_t a, uint32_t parity) {
    asm volatile(
        "{\n\t.reg .pred P;\n"
        "WL_%=:\n\t"
        "mbarrier.try_wait.parity.acquire.cta.shared::cta.b64 P, [%0], %1, 0x989680;\n\t"
        "@P bra WD_%=;\n\t"
        "bra WL_%=;\n"
        "WD_%=:\n\t}"
        ::"r"(a), "r"(parity) : "memory");
}
__device__ __forceinline__ void ldsm4(uint32_t* r, uint32_t addr) {
    asm volatile("ldmatrix.sync.aligned.m8n8.x4.shared.b16 {%0,%1,%2,%3}, [%4];"
                 : "=r"(r[0]), "=r"(r[1]), "=r"(r[2]), "=r"(r[3])
                 : "r"(addr));
}
__device__ __forceinline__ void mma16816(float* d, const uint32_t* a, uint32_t b0, uint32_t b1) {
    asm volatile(
        "mma.sync.aligned.m16n8k16.row.col.f32.f16.f16.f32 "
        "{%0,%1,%2,%3}, {%4,%5,%6,%7}, {%8,%9}, {%0,%1,%2,%3};"
        : "+f"(d[0]), "+f"(d[1]), "+f"(d[2]), "+f"(d[3])
        : "r"(a[0]), "r"(a[1]), "r"(a[2]), "r"(a[3]), "r"(b0), "r"(b1));
}

// ---------------- unified pack kernel (round-15, unchanged) ----------------
constexpr int NB_X  = 8192;
constexpr int NB_W  = 22528;
constexpr int NB_ALL = NB_X + 3 * NB_W;   // 75776

__device__ void pack_x_blk(const float4* __restrict__ x, int bi) {
    const int kb = bi & 15, mb = (bi >> 4) & 15, be = bi >> 8;
    const float4* src = x + ((size_t)be * C_ + mb * 128) * (D_ / 4) + kb * 16;
    char* dst = (char*)g_xa + (((size_t)be * 16 + mb) * 16 + kb) * TILE_A;
    const int tid = threadIdx.x;
#pragma unroll
    for (int j = 0; j < 8; j++) {
        int t = tid + j * 256;
        int r = t >> 4, c = t & 15;
        float4 v = src[(size_t)r * (D_ / 4) + c];
        uint2 p;
        __half2 h0 = __floats2half2_rn(v.x, v.y);
        __half2 h1 = __floats2half2_rn(v.z, v.w);
        p.x = *reinterpret_cast<uint32_t*>(&h0);
        p.y = *reinterpret_cast<uint32_t*>(&h1);
        *reinterpret_cast<uint2*>(dst + swz(r * 128 + c * 8)) = p;
    }
}

__device__ void pack_w13_blk(const float* __restrict__ w, int rowoff, int bi,
                             float t[32][33]) {
    const int fb = bi % 88, db = (bi / 88) % 32, e = bi / (88 * 32);
    const int f0 = fb * 32, d0 = db * 32;
    const float* src = w + (size_t)e * D_ * F_;
    const int tx = threadIdx.x & 31, ty = threadIdx.x >> 5;
#pragma unroll
    for (int i = 0; i < 4; i++)
        t[ty + 8 * i][tx] = src[(size_t)(d0 + ty + 8 * i) * F_ + f0 + tx];
    __syncthreads();
    const int lin = threadIdx.x;
#pragma unroll
    for (int i = 0; i < 2; i++) {
        int idx = lin + 256 * i;
        int fl = idx >> 4, dp = idx & 15;
        int n = f0 + fl;
        int nb = n >> 6, row = (n & 63) + rowoff;
        int d = d0 + 2 * dp;
        int kb = d >> 6, cd = d & 63;
        char* dst = (char*)g_wa + (((size_t)e * 44 + nb) * 16 + kb) * TILE_B;
        *reinterpret_cast<__half2*>(dst + swz(row * 128 + cd * 2)) =
            __floats2half2_rn(t[2 * dp][fl], t[2 * dp + 1][fl]);
    }
}

__device__ void pack_w2_blk(const float* __restrict__ w, int bi, float t[32][33]) {
    const int db = bi % 32, fb = (bi / 32) % 88, e = bi / (32 * 88);
    const int d0 = db * 32, f0 = fb * 32;
    const float* src = w + (size_t)e * F_ * D_;
    const int tx = threadIdx.x & 31, ty = threadIdx.x >> 5;
#pragma unroll
    for (int i = 0; i < 4; i++)
        t[ty + 8 * i][tx] = src[(size_t)(f0 + ty + 8 * i) * D_ + d0 + tx];
    __syncthreads();
    const int lin = threadIdx.x;
#pragma unroll
    for (int i = 0; i < 2; i++) {
        int idx = lin + 256 * i;
        int dl = idx >> 4, fp = idx & 15;
        int n = d0 + dl;
        int nb = n >> 7, row = n & 127;
        int f = f0 + 2 * fp;
        int kb = f >> 6, cf = f & 63;
        char* dst = (char*)g_w2a + (((size_t)e * 8 + nb) * 44 + kb) * TILE_B;
        *reinterpret_cast<__half2*>(dst + swz(row * 128 + cf * 2)) =
            __floats2half2_rn(t[2 * fp][dl], t[2 * fp + 1][dl]);
    }
}

__global__ __launch_bounds__(256) void pack_all(const float4* __restrict__ x,
                                                const float* __restrict__ w1,
                                                const float* __restrict__ w3,
                                                const float* __restrict__ w2) {
    __shared__ float t[32][33];
    const int b = blockIdx.x;
    if (b < NB_X) {
        pack_x_blk(x, b);
    } else if (b < NB_X + NB_W) {
        pack_w13_blk(w1, 0, b - NB_X, t);
    } else if (b < NB_X + 2 * NB_W) {
        pack_w13_blk(w3, 64, b - NB_X - NB_W, t);
    } else {
        pack_w2_blk(w2, b - NB_X - 2 * NB_W, t);
    }
}

// ============================================================
// mma.sync GEMM (round-15 structure): 256 threads, CTA 128x128, BK=64,
// 3 stages x 32KB, 2 CTAs/SM, whole-tile bulk G2S, pair-unrolled mainloop.
// NEW: split-producer issue — tid 0 does expect_tx + A copy, tid 32 issues
// the B copy (same mbarrier; tx-count semantics make order irrelevant).
// ============================================================
constexpr int STG   = TILE_A + TILE_B;   // 32768
constexpr int DYNSM = 3 * STG;           // 98304

template <int G1>
__global__ __launch_bounds__(256, 2) void gemm_mma(float* __restrict__ out) {
    extern __shared__ __align__(128) char smem[];
    __shared__ __align__(8) uint64_t fullb[3];

    const int tid  = threadIdx.x;
    const int wid  = tid >> 5;
    const int lane = tid & 31;
    const int be   = blockIdx.z, e = be & 7;
    const int mblk = blockIdx.y;
    const int nblk = blockIdx.x;

    constexpr int NK = G1 ? 16 : 44;     // both even

    const char* Atile;
    const char* Btile;
    if (G1) {
        Atile = (const char*)g_xa + (((size_t)be * 16 + mblk) * 16) * TILE_A;
        Btile = (const char*)g_wa + (((size_t)e * 44 + nblk) * 16) * TILE_B;
    } else {
        Atile = (const char*)g_ha  + (((size_t)be * 16 + mblk) * 44) * TILE_A;
        Btile = (const char*)g_w2a + (((size_t)e * 8 + nblk) * 44) * TILE_B;
    }

    const uint32_t sb = smem_u32(smem);
    const uint32_t fb = smem_u32(fullb);

    if (tid == 0) {
#pragma unroll
        for (int i = 0; i < 3; i++) mbar_init(fb + 8 * i, 1);
    }
    __syncthreads();

    // split-producer issue: tid 0 -> expect_tx + A copy; tid 32 -> B copy.
    auto issueA = [&](int kt) {
        const int s = kt % 3;
        mbar_expect_tx(fb + 8 * s, STG);
        bulk_cp(sb + s * STG, Atile + (size_t)kt * TILE_A, TILE_A, fb + 8 * s);
    };
    auto issueB = [&](int kt) {
        const int s = kt % 3;
        bulk_cp(sb + s * STG + TILE_A, Btile + (size_t)kt * TILE_B, TILE_B, fb + 8 * s);
    };

    if (tid == 0)  { issueA(0); issueA(1); issueA(2); }
    if (tid == 32) { issueB(0); issueB(1); issueB(2); }

    const int wm = wid >> 2;             // 0..1 : M rows [wm*64, +64)
    const int wn = wid & 3;              // 0..3
    const int lr = lane & 15;
    const int lk = (lane >> 4) * 16;

    float acc0[4][2][4], acc1[4][2][4];
#pragma unroll
    for (int i = 0; i < 4; i++)
#pragma unroll
        for (int j = 0; j < 2; j++)
#pragma unroll
            for (int q = 0; q < 4; q++) { acc0[i][j][q] = 0.f; acc1[i][j][q] = 0.f; }

    auto consume = [&](int kt) {
        const int s = kt % 3;
        mbar_wait(fb + 8 * s, (kt / 3) & 1);
        const uint32_t sA = sb + s * STG;
        const uint32_t sB = sA + TILE_A;
#pragma unroll
        for (int kk = 0; kk < 4; kk++) {
            uint32_t af[4][4];
#pragma unroll
            for (int mt = 0; mt < 4; mt++)
                ldsm4(af[mt], sA + swz((wm * 64 + mt * 16 + lr) * 128 + kk * 32 + lk));

            uint32_t b0r[4], b1r[4];
            if (G1) {
                ldsm4(b0r, sB + swz((wn * 16 + lr) * 128 + kk * 32 + lk));        // gate
                ldsm4(b1r, sB + swz((64 + wn * 16 + lr) * 128 + kk * 32 + lk));   // up
            } else {
                ldsm4(b0r, sB + swz((wn * 32 + lr) * 128 + kk * 32 + lk));
                ldsm4(b1r, sB + swz((wn * 32 + 16 + lr) * 128 + kk * 32 + lk));
            }
#pragma unroll
            for (int mt = 0; mt < 4; mt++)
#pragma unroll
                for (int hi = 0; hi < 2; hi++) {
                    mma16816(acc0[mt][hi], af[mt], b0r[hi], b0r[hi + 2]);
                    mma16816(acc1[mt][hi], af[mt], b1r[hi], b1r[hi + 2]);
                }
        }
    };

    // pair-unrolled mainloop: one barrier + one issue-burst per 2 stages.
    for (int kt = 0; kt < NK; kt += 2) {
        if (kt >= 2) {
            __syncthreads();
            if (tid == 0) {
                issueA(kt + 1);
                if (kt + 2 < NK) issueA(kt + 2);
            }
            if (tid == 32) {
                issueB(kt + 1);
                if (kt + 2 < NK) issueB(kt + 2);
            }
        }
        consume(kt);
        consume(kt + 1);
    }

    // ---------------- epilogue ----------------
    const int lr4 = lane >> 2;
    const int c0  = (lane & 3) * 2;

    if (G1) {
        __syncthreads();
        const uint32_t hstage = sb;
#pragma unroll
        for (int mt = 0; mt < 4; mt++) {
#pragma unroll
            for (int h = 0; h < 2; h++) {
                const int r128 = wm * 64 + mt * 16 + h * 8 + lr4;
#pragma unroll
                for (int hi = 0; hi < 2; hi++) {
                    const int nc = wn * 16 + hi * 8 + c0;
                    float g0 = acc0[mt][hi][2 * h + 0], g1 = acc0[mt][hi][2 * h + 1];
                    float u0 = acc1[mt][hi][2 * h + 0], u1 = acc1[mt][hi][2 * h + 1];
                    float h0 = u0 * g0 / (1.0f + __expf(-g0));
                    float h1 = u1 * g1 / (1.0f + __expf(-g1));
                    __half2 hv = __floats2half2_rn(h0, h1);
                    asm volatile("st.shared.b32 [%0], %1;"
                                 ::"r"(hstage + swz(r128 * 128 + nc * 2)),
                                   "r"(*reinterpret_cast<uint32_t*>(&hv)) : "memory");
                }
            }
        }
        fence_async_smem();
        __syncthreads();
        if (tid == 0) {
            char* dst = (char*)g_ha + (((size_t)be * 16 + mblk) * 44 + nblk) * TILE_A;
            bulk_s2g(dst, hstage, TILE_A);
            bulk_commit();
            bulk_wait0();
        }
    } else {
        const int rbase = mblk * 128 + wm * 64 + lr4;
        const int n0    = nblk * 128;
#pragma unroll
        for (int mt = 0; mt < 4; mt++) {
#pragma unroll
            for (int h = 0; h < 2; h++) {
                const size_t row = (size_t)be * C_ + rbase + mt * 16 + h * 8;
                float* orow = out + row * D_ + n0 + wn * 32 + c0;
#pragma unroll
                for (int hi = 0; hi < 2; hi++) {
                    *reinterpret_cast<float2*>(orow + hi * 8) =
                        make_float2(acc0[mt][hi][2 * h + 0], acc0[mt][hi][2 * h + 1]);
                    *reinterpret_cast<float2*>(orow + 16 + hi * 8) =
                        make_float2(acc1[mt][hi][2 * h + 0], acc1[mt][hi][2 * h + 1]);
                }
            }
        }
    }
}

// ---------------- launch ----------------
extern "C" void kernel_launch(void* const* d_in, const int* in_sizes, int n_in,
                              void* d_out, int out_size) {
    const float* x  = (const float*)d_in[0];
    const float* w1 = (const float*)d_in[1];
    const float* w3 = (const float*)d_in[2];
    const float* w2 = (const float*)d_in[3];
    float* out = (float*)d_out;

    cudaFuncSetAttribute(gemm_mma<1>, cudaFuncAttributeMaxDynamicSharedMemorySize, DYNSM);
    cudaFuncSetAttribute(gemm_mma<0>, cudaFuncAttributeMaxDynamicSharedMemorySize, DYNSM);

    pack_all<<<NB_ALL, 256>>>((const float4*)x, w1, w3, w2);

    gemm_mma<1><<<dim3(44, 16, 32), 256, DYNSM>>>(nullptr);
    gemm_mma<0><<<dim3(8, 16, 32), 256, DYNSM>>>(out);
}